// round 7
// baseline (speedup 1.0000x reference)
#include <cuda_runtime.h>
#include <cstdint>
#include <cstddef>

#define TOKENS 8192
#define HDIM 1024
#define FFDIM 4096
#define NEXP 8
#define SLOTS (TOKENS*2)
#define RBLOCKS (TOKENS/8)

// ---------------- scratch (device globals; no allocation allowed) ----------------
__device__ float g_H[(size_t)SLOTS * FFDIM];   // silu(gate)*up per slot
__device__ float g_O[(size_t)SLOTS * HDIM];    // per-slot expert output
__device__ int   g_perm[SLOTS];
__device__ int   g_slot_of[TOKENS*2];
__device__ float g_score[TOKENS*2];
__device__ int   g_eidx[TOKENS*2];
__device__ int   g_offsets[NEXP+1];
__device__ float g_zpart[RBLOCKS];
__device__ float g_ppart[RBLOCKS*NEXP];

// ---------------- helpers ----------------
__device__ __forceinline__ uint32_t f2tf(float f) {
    uint32_t r; asm("cvt.rna.tf32.f32 %0, %1;" : "=r"(r) : "f"(f)); return r;
}
__device__ __forceinline__ uint32_t tf_of(uint32_t raw) {
    return f2tf(__uint_as_float(raw));
}
__device__ __forceinline__ void mma_tf32(float c[4], const uint32_t a[4], const uint32_t b[2]) {
    asm volatile(
        "mma.sync.aligned.m16n8k8.row.col.f32.tf32.tf32.f32 "
        "{%0,%1,%2,%3}, {%4,%5,%6,%7}, {%8,%9}, {%0,%1,%2,%3};\n"
        : "+f"(c[0]), "+f"(c[1]), "+f"(c[2]), "+f"(c[3])
        : "r"(a[0]), "r"(a[1]), "r"(a[2]), "r"(a[3]), "r"(b[0]), "r"(b[1]));
}
__device__ __forceinline__ void cpa16(uint32_t saddr, const void* gsrc, int srcbytes) {
    asm volatile("cp.async.cg.shared.global [%0], [%1], 16, %2;\n"
                 :: "r"(saddr), "l"(gsrc), "r"(srcbytes));
}
__device__ __forceinline__ void cpa_commit() {
    asm volatile("cp.async.commit_group;\n" ::: "memory");
}
template <int N>
__device__ __forceinline__ void cpa_wait() {
    asm volatile("cp.async.wait_group %0;\n" :: "n"(N) : "memory");
}
__device__ __forceinline__ uint32_t smem_u32(const void* p) {
    return (uint32_t)__cvta_generic_to_shared(p);
}

// ---------------- router: one warp per token ----------------
__global__ void router_kernel(const float* __restrict__ x, const float* __restrict__ wr) {
    __shared__ float s_z[8];
    __shared__ float s_p[8][NEXP];
    int warp = threadIdx.x >> 5, lane = threadIdx.x & 31;
    int t = blockIdx.x * 8 + warp;
    const float* xr = x + (size_t)t * HDIM;
    float acc[NEXP];
#pragma unroll
    for (int e = 0; e < NEXP; e++) acc[e] = 0.f;
    for (int i = lane; i < HDIM; i += 32) {
        float xv = xr[i];
        const float4* w4 = reinterpret_cast<const float4*>(wr + (size_t)i * NEXP);
        float4 w0 = w4[0], w1 = w4[1];
        acc[0] += xv * w0.x; acc[1] += xv * w0.y; acc[2] += xv * w0.z; acc[3] += xv * w0.w;
        acc[4] += xv * w1.x; acc[5] += xv * w1.y; acc[6] += xv * w1.z; acc[7] += xv * w1.w;
    }
#pragma unroll
    for (int e = 0; e < NEXP; e++)
#pragma unroll
        for (int o = 16; o > 0; o >>= 1) acc[e] += __shfl_xor_sync(0xffffffffu, acc[e], o);

    if (lane == 0) {
        float z = 0.f, mx = acc[0];
#pragma unroll
        for (int e = 0; e < NEXP; e++) { z += acc[e] * acc[e]; mx = fmaxf(mx, acc[e]); }
        float p[NEXP], s = 0.f;
#pragma unroll
        for (int e = 0; e < NEXP; e++) { p[e] = expf(acc[e] - mx); s += p[e]; }
        float inv = 1.f / s;
#pragma unroll
        for (int e = 0; e < NEXP; e++) p[e] *= inv;
        int i0 = 0;
#pragma unroll
        for (int e = 1; e < NEXP; e++) if (p[e] > p[i0]) i0 = e;
        int i1 = (i0 == 0) ? 1 : 0;
#pragma unroll
        for (int e = 0; e < NEXP; e++) if (e != i0 && p[e] > p[i1]) i1 = e;
        float s0 = p[i0], s1 = p[i1], sn = 1.f / (s0 + s1);
        g_eidx[t*2] = i0;  g_eidx[t*2+1] = i1;
        g_score[t*2] = s0 * sn; g_score[t*2+1] = s1 * sn;
        s_z[warp] = z;
#pragma unroll
        for (int e = 0; e < NEXP; e++) s_p[warp][e] = p[e];
    }
    __syncthreads();
    if (threadIdx.x == 0) {
        float z = 0.f;
#pragma unroll
        for (int w = 0; w < 8; w++) z += s_z[w];
        g_zpart[blockIdx.x] = z;
    }
    if (threadIdx.x < NEXP) {
        float ps = 0.f;
#pragma unroll
        for (int w = 0; w < 8; w++) ps += s_p[w][threadIdx.x];
        g_ppart[blockIdx.x * NEXP + threadIdx.x] = ps;
    }
}

// ---------------- fused count + scan + scatter (single block) ----------------
__global__ void route_kernel() {
    __shared__ int s_cnt[NEXP];
    __shared__ int s_cur[NEXP];
    int tid = threadIdx.x;                 // 1024 threads
    if (tid < NEXP) s_cnt[tid] = 0;
    __syncthreads();
    for (int i = tid; i < TOKENS*2; i += 1024)
        atomicAdd(&s_cnt[g_eidx[i]], 1);
    __syncthreads();
    if (tid == 0) {
        int o = 0;
        for (int e = 0; e < NEXP; e++) { g_offsets[e] = o; s_cur[e] = o; o += s_cnt[e]; }
        g_offsets[NEXP] = o;
    }
    __syncthreads();
    for (int i = tid; i < TOKENS*2; i += 1024) {
        int e = g_eidx[i];
        int pos = atomicAdd(&s_cur[e], 1);
        g_perm[pos] = i >> 1;
        g_slot_of[i] = pos;
    }
}

// =======================================================================================
// GEMM1: H[slot,:] = silu(X@Wg) * (X@Wu)   fused, tf32, 2-stage cp.async
// BM=256, BN=64 per matrix, BK=32. 512 threads, warp grid 4(M)x4(N), warp tile 64x16.
// =======================================================================================
#define G1_AS (256*36)
#define G1_BS (32*72)
#define G1_SMEM ((2*G1_AS + 4*G1_BS) * 4)   // 147456... (2*9216 + 4*2304)*4 = 110592 B
__global__ __launch_bounds__(512) void gemm1_kernel(const float* __restrict__ x,
                                                    const float* __restrict__ w_gate,
                                                    const float* __restrict__ w_up) {
    const int e = blockIdx.z;
    const int off = g_offsets[e];
    const int cnt = g_offsets[e+1] - off;
    const int m0 = blockIdx.y * 256;
    if (m0 >= cnt) return;
    const int n0 = blockIdx.x * 64;

    extern __shared__ uint32_t smem[];
    uint32_t* As = smem;                 // 2 * G1_AS
    uint32_t* Bg = smem + 2*G1_AS;       // 2 * G1_BS
    uint32_t* Bu = Bg + 2*G1_BS;         // 2 * G1_BS

    const int tid = threadIdx.x, lane = tid & 31, wid = tid >> 5;
    const int wm = (wid & 3) * 64, wn = (wid >> 2) * 16;

    // A: 2048 chunks of 16B (256 rows x 8), 4 per thread
    const int ac4 = tid & 7;
    const float* aptr[4]; int avalid[4]; uint32_t a_dst[4];
#pragma unroll
    for (int i = 0; i < 4; i++) {
        int r = (tid >> 3) + i * 64;
        int m = m0 + r;
        avalid[i] = (m < cnt) ? 16 : 0;
        aptr[i] = (m < cnt) ? (x + (size_t)g_perm[off + m] * HDIM + ac4 * 4) : x;
        a_dst[i] = smem_u32(&As[r*36 + ac4*4]);
    }
    // B: 512 chunks per matrix (32 rows x 16), 1 per thread
    const int bc4 = tid & 15;
    const int brow = tid >> 4;
    const float* gptr; const float* uptr; uint32_t g_dst, u_dst;
    {
        size_t o = (size_t)e * HDIM * FFDIM + (size_t)brow * FFDIM + n0 + bc4 * 4;
        gptr = w_gate + o; uptr = w_up + o;
        g_dst = smem_u32(&Bg[brow*72 + bc4*4]);
        u_dst = smem_u32(&Bu[brow*72 + bc4*4]);
    }

    float cg[4][2][4], cu[4][2][4];
#pragma unroll
    for (int mi = 0; mi < 4; mi++)
#pragma unroll
        for (int ni = 0; ni < 2; ni++)
#pragma unroll
            for (int j = 0; j < 4; j++) { cg[mi][ni][j] = 0.f; cu[mi][ni][j] = 0.f; }

    const int NSTEP = HDIM / 32;

    // prologue: stage 0
#pragma unroll
    for (int i = 0; i < 4; i++) cpa16(a_dst[i], aptr[i], avalid[i]);
    cpa16(g_dst, gptr, 16);
    cpa16(u_dst, uptr, 16);
    cpa_commit();

    for (int s = 0; s < NSTEP; s++) {
        const int cur = s & 1;
        if (s + 1 < NSTEP) {
            const int nxt = (s + 1) & 1;
            const int k0 = (s + 1) * 32;
            const uint32_t ao = nxt * G1_AS * 4, bo = nxt * G1_BS * 4;
#pragma unroll
            for (int i = 0; i < 4; i++) cpa16(a_dst[i] + ao, aptr[i] + k0, avalid[i]);
            cpa16(g_dst + bo, gptr + (size_t)k0 * FFDIM, 16);
            cpa16(u_dst + bo, uptr + (size_t)k0 * FFDIM, 16);
            cpa_commit();
            cpa_wait<1>();
        } else {
            cpa_wait<0>();
        }
        __syncthreads();

        const uint32_t* A  = As + cur * G1_AS;
        const uint32_t* BG = Bg + cur * G1_BS;
        const uint32_t* BU = Bu + cur * G1_BS;

#pragma unroll
        for (int kk = 0; kk < 4; kk++) {
            uint32_t a[4][4];
            const int fr = lane >> 2, fc = lane & 3;
#pragma unroll
            for (int mi = 0; mi < 4; mi++) {
                int rb = wm + mi * 16;
                a[mi][0] = tf_of(A[(rb+fr  )*36 + kk*8 + fc    ]);
                a[mi][1] = tf_of(A[(rb+fr+8)*36 + kk*8 + fc    ]);
                a[mi][2] = tf_of(A[(rb+fr  )*36 + kk*8 + fc + 4]);
                a[mi][3] = tf_of(A[(rb+fr+8)*36 + kk*8 + fc + 4]);
            }
            uint32_t bgf[2][2], buf[2][2];
            const int bk = lane & 3, bn = lane >> 2;
#pragma unroll
            for (int ni = 0; ni < 2; ni++) {
                int nb = wn + ni * 8;
                bgf[ni][0] = tf_of(BG[(kk*8+bk  )*72 + nb + bn]);
                bgf[ni][1] = tf_of(BG[(kk*8+bk+4)*72 + nb + bn]);
                buf[ni][0] = tf_of(BU[(kk*8+bk  )*72 + nb + bn]);
                buf[ni][1] = tf_of(BU[(kk*8+bk+4)*72 + nb + bn]);
            }
#pragma unroll
            for (int mi = 0; mi < 4; mi++)
#pragma unroll
                for (int ni = 0; ni < 2; ni++) {
                    mma_tf32(cg[mi][ni], a[mi], bgf[ni]);
                    mma_tf32(cu[mi][ni], a[mi], buf[ni]);
                }
        }
        __syncthreads();
    }

    const int fr = lane >> 2, fc2 = (lane & 3) * 2;
#pragma unroll
    for (int mi = 0; mi < 4; mi++) {
        int r1 = wm + mi * 16 + fr;
        int m1 = m0 + r1, m2 = m1 + 8;
#pragma unroll
        for (int ni = 0; ni < 2; ni++) {
            int col = n0 + wn + ni * 8 + fc2;
            if (m1 < cnt) {
                int slot = off + m1;
                float g0 = cg[mi][ni][0], g1 = cg[mi][ni][1];
                float u0 = cu[mi][ni][0], u1 = cu[mi][ni][1];
                float h0 = g0 / (1.f + expf(-g0)) * u0;
                float h1 = g1 / (1.f + expf(-g1)) * u1;
                *reinterpret_cast<float2*>(&g_H[(size_t)slot * FFDIM + col]) = make_float2(h0, h1);
            }
            if (m2 < cnt) {
                int slot = off + m2;
                float g0 = cg[mi][ni][2], g1 = cg[mi][ni][3];
                float u0 = cu[mi][ni][2], u1 = cu[mi][ni][3];
                float h0 = g0 / (1.f + expf(-g0)) * u0;
                float h1 = g1 / (1.f + expf(-g1)) * u1;
                *reinterpret_cast<float2*>(&g_H[(size_t)slot * FFDIM + col]) = make_float2(h0, h1);
            }
        }
    }
}

// =======================================================================================
// GEMM2: O[slot,:] = H[slot,:] @ Wd[e]   tf32, 2-stage cp.async
// BM=256, BN=128, BK=32. 512 threads, warp grid 4(M)x4(N), warp tile 64x32.
// =======================================================================================
#define G2_AS (256*36)
#define G2_BS (32*136)
#define G2_SMEM ((2*G2_AS + 2*G2_BS) * 4)   // (18432 + 8704)*4 = 108544 B
__global__ __launch_bounds__(512) void gemm2_kernel(const float* __restrict__ w_down) {
    const int e = blockIdx.z;
    const int off = g_offsets[e];
    const int cnt = g_offsets[e+1] - off;
    const int m0 = blockIdx.y * 256;
    if (m0 >= cnt) return;
    const int n0 = blockIdx.x * 128;

    extern __shared__ uint32_t smem[];
    uint32_t* As = smem;             // 2 * G2_AS
    uint32_t* Bs = smem + 2*G2_AS;   // 2 * G2_BS

    const int tid = threadIdx.x, lane = tid & 31, wid = tid >> 5;
    const int wm = (wid & 3) * 64, wn = (wid >> 2) * 32;

    // A: 2048 chunks, 4 per thread
    const int ac4 = tid & 7;
    const float* aptr[4]; int avalid[4]; uint32_t a_dst[4];
#pragma unroll
    for (int i = 0; i < 4; i++) {
        int r = (tid >> 3) + i * 64;
        int m = m0 + r;
        avalid[i] = (m < cnt) ? 16 : 0;
        aptr[i] = (m < cnt) ? (g_H + (size_t)(off + m) * FFDIM + ac4 * 4) : g_H;
        a_dst[i] = smem_u32(&As[r*36 + ac4*4]);
    }
    // B: 1024 chunks (32 rows x 32), 2 per thread
    const float* bptr[2]; uint32_t b_dst[2];
#pragma unroll
    for (int i = 0; i < 2; i++) {
        int q = tid + i * 512;
        int r = q >> 5, c4 = q & 31;
        bptr[i] = w_down + (size_t)e * FFDIM * HDIM + (size_t)r * HDIM + n0 + c4 * 4;
        b_dst[i] = smem_u32(&Bs[r*136 + c4*4]);
    }

    float c[4][4][4];
#pragma unroll
    for (int mi = 0; mi < 4; mi++)
#pragma unroll
        for (int ni = 0; ni < 4; ni++)
#pragma unroll
            for (int j = 0; j < 4; j++) c[mi][ni][j] = 0.f;

    const int NSTEP = FFDIM / 32;

#pragma unroll
    for (int i = 0; i < 4; i++) cpa16(a_dst[i], aptr[i], avalid[i]);
#pragma unroll
    for (int i = 0; i < 2; i++) cpa16(b_dst[i], bptr[i], 16);
    cpa_commit();

    for (int s = 0; s < NSTEP; s++) {
        const int cur = s & 1;
        if (s + 1 < NSTEP) {
            const int nxt = (s + 1) & 1;
            const int k0 = (s + 1) * 32;
            const uint32_t ao = nxt * G2_AS * 4, bo = nxt * G2_BS * 4;
#pragma unroll
            for (int i = 0; i < 4; i++) cpa16(a_dst[i] + ao, aptr[i] + k0, avalid[i]);
#pragma unroll
            for (int i = 0; i < 2; i++) cpa16(b_dst[i] + bo, bptr[i] + (size_t)k0 * HDIM, 16);
            cpa_commit();
            cpa_wait<1>();
        } else {
            cpa_wait<0>();
        }
        __syncthreads();

        const uint32_t* A = As + cur * G2_AS;
        const uint32_t* B = Bs + cur * G2_BS;

#pragma unroll
        for (int kk = 0; kk < 4; kk++) {
            uint32_t a[4][4];
            const int fr = lane >> 2, fc = lane & 3;
#pragma unroll
            for (int mi = 0; mi < 4; mi++) {
                int rb = wm + mi * 16;
                a[mi][0] = tf_of(A[(rb+fr  )*36 + kk*8 + fc    ]);
                a[mi][1] = tf_of(A[(rb+fr+8)*36 + kk*8 + fc    ]);
                a[mi][2] = tf_of(A[(rb+fr  )*36 + kk*8 + fc + 4]);
                a[mi][3] = tf_of(A[(rb+fr+8)*36 + kk*8 + fc + 4]);
            }
            uint32_t b[4][2];
            const int bk = lane & 3, bn = lane >> 2;
#pragma unroll
            for (int ni = 0; ni < 4; ni++) {
                int nb = wn + ni * 8;
                b[ni][0] = tf_of(B[(kk*8+bk  )*136 + nb + bn]);
                b[ni][1] = tf_of(B[(kk*8+bk+4)*136 + nb + bn]);
            }
#pragma unroll
            for (int mi = 0; mi < 4; mi++)
#pragma unroll
                for (int ni = 0; ni < 4; ni++)
                    mma_tf32(c[mi][ni], a[mi], b[ni]);
        }
        __syncthreads();
    }

    const int fr = lane >> 2, fc2 = (lane & 3) * 2;
#pragma unroll
    for (int mi = 0; mi < 4; mi++) {
        int r1 = wm + mi * 16 + fr;
        int m1 = m0 + r1, m2 = m1 + 8;
#pragma unroll
        for (int ni = 0; ni < 4; ni++) {
            int col = n0 + wn + ni * 8 + fc2;
            if (m1 < cnt)
                *reinterpret_cast<float2*>(&g_O[(size_t)(off+m1) * HDIM + col]) =
                    make_float2(c[mi][ni][0], c[mi][ni][1]);
            if (m2 < cnt)
                *reinterpret_cast<float2*>(&g_O[(size_t)(off+m2) * HDIM + col]) =
                    make_float2(c[mi][ni][2], c[mi][ni][3]);
        }
    }
}

// ---------------- combine + losses ----------------
__global__ void combine_kernel(float* __restrict__ out) {
    int idx = blockIdx.x * blockDim.x + threadIdx.x;
    int t = idx >> 8;
    int c4 = idx & 255;
    if (t >= TOKENS) return;
    int s0 = g_slot_of[t*2], s1 = g_slot_of[t*2+1];
    float w0 = g_score[t*2], w1 = g_score[t*2+1];
    float4 a = *reinterpret_cast<const float4*>(&g_O[(size_t)s0 * HDIM + c4*4]);
    float4 b = *reinterpret_cast<const float4*>(&g_O[(size_t)s1 * HDIM + c4*4]);
    float4 o;
    o.x = w0*a.x + w1*b.x; o.y = w0*a.y + w1*b.y;
    o.z = w0*a.z + w1*b.z; o.w = w0*a.w + w1*b.w;
    *reinterpret_cast<float4*>(&out[(size_t)t * HDIM + c4*4]) = o;
}

__global__ void loss_kernel(float* __restrict__ out) {
    int lane = threadIdx.x;
    float z = 0.f, pe[NEXP];
#pragma unroll
    for (int e = 0; e < NEXP; e++) pe[e] = 0.f;
    for (int i = lane; i < RBLOCKS; i += 32) {
        z += g_zpart[i];
#pragma unroll
        for (int e = 0; e < NEXP; e++) pe[e] += g_ppart[i*NEXP + e];
    }
#pragma unroll
    for (int o = 16; o > 0; o >>= 1) {
        z += __shfl_xor_sync(0xffffffffu, z, o);
#pragma unroll
        for (int e = 0; e < NEXP; e++) pe[e] += __shfl_xor_sync(0xffffffffu, pe[e], o);
    }
    if (lane == 0) {
        float zl = (float)NEXP * (z / (float)((size_t)TOKENS * NEXP));
        float aux = 0.f;
#pragma unroll
        for (int e = 0; e < NEXP; e++) {
            float pm = pe[e] / (float)TOKENS;
            aux += pm * logf(pm + 1e-9f);
        }
        out[(size_t)TOKENS * HDIM    ] = zl;
        out[(size_t)TOKENS * HDIM + 1] = (float)NEXP * aux;
    }
}

// ---------------- launch ----------------
extern "C" void kernel_launch(void* const* d_in, const int* in_sizes, int n_in,
                              void* d_out, int out_size) {
    const float* x        = (const float*)d_in[0];
    const float* w_router = (const float*)d_in[1];
    const float* w_gate   = (const float*)d_in[2];
    const float* w_up     = (const float*)d_in[3];
    const float* w_down   = (const float*)d_in[4];
    float* out = (float*)d_out;

    cudaFuncSetAttribute(gemm1_kernel, cudaFuncAttributeMaxDynamicSharedMemorySize, G1_SMEM);
    cudaFuncSetAttribute(gemm2_kernel, cudaFuncAttributeMaxDynamicSharedMemorySize, G2_SMEM);

    router_kernel<<<RBLOCKS, 256>>>(x, w_router);                         // 1
    route_kernel<<<1, 1024>>>();                                          // 2
    gemm1_kernel<<<dim3(FFDIM/64, 32, NEXP), 512, G1_SMEM>>>(x, w_gate, w_up);  // 3
    gemm2_kernel<<<dim3(HDIM/128, 32, NEXP), 512, G2_SMEM>>>(w_down);     // 4 <- profiled
    combine_kernel<<<(TOKENS*256)/256, 256>>>(out);                       // 5
    loss_kernel<<<1, 32>>>(out);                                          // 6
}

// round 8
// speedup vs baseline: 1.7400x; 1.7400x over previous
#include <cuda_runtime.h>
#include <cuda_fp16.h>
#include <cstdint>
#include <cstddef>

#define TOKENS 8192
#define HDIM 1024
#define FFDIM 4096
#define NEXP 8
#define SLOTS (TOKENS*2)
#define RBLOCKS (TOKENS/8)

// ---------------- scratch (device globals; no allocation allowed) ----------------
__device__ __half g_Xh[(size_t)TOKENS * HDIM];          // 16 MB  fp16 x
__device__ __half g_WgT[(size_t)NEXP * FFDIM * HDIM];   // 64 MB  w_gate^T [e][ff][h] fp16
__device__ __half g_WuT[(size_t)NEXP * FFDIM * HDIM];   // 64 MB  w_up^T
__device__ __half g_WdT[(size_t)NEXP * HDIM * FFDIM];   // 64 MB  w_down^T [e][h][ff]
__device__ __half g_Hh[(size_t)SLOTS * FFDIM];          // 128 MB fp16 silu(gate)*up
__device__ float  g_O[(size_t)SLOTS * HDIM];            // 64 MB  per-slot output (fp32)
__device__ int    g_perm[SLOTS];
__device__ int    g_slot_of[TOKENS*2];
__device__ float  g_score[TOKENS*2];
__device__ int    g_eidx[TOKENS*2];
__device__ int    g_offsets[NEXP+1];
__device__ float  g_zpart[RBLOCKS];
__device__ float  g_ppart[RBLOCKS*NEXP];

// ---------------- helpers ----------------
__device__ __forceinline__ void mma_f16(float c[4], const uint32_t a[4], const uint32_t b[2]) {
    asm volatile(
        "mma.sync.aligned.m16n8k16.row.col.f32.f16.f16.f32 "
        "{%0,%1,%2,%3}, {%4,%5,%6,%7}, {%8,%9}, {%0,%1,%2,%3};\n"
        : "+f"(c[0]), "+f"(c[1]), "+f"(c[2]), "+f"(c[3])
        : "r"(a[0]), "r"(a[1]), "r"(a[2]), "r"(a[3]), "r"(b[0]), "r"(b[1]));
}
__device__ __forceinline__ void cpa16(uint32_t saddr, const void* gsrc, int srcbytes) {
    asm volatile("cp.async.cg.shared.global [%0], [%1], 16, %2;\n"
                 :: "r"(saddr), "l"(gsrc), "r"(srcbytes));
}
__device__ __forceinline__ void cpa_commit() {
    asm volatile("cp.async.commit_group;\n" ::: "memory");
}
template <int N>
__device__ __forceinline__ void cpa_wait() {
    asm volatile("cp.async.wait_group %0;\n" :: "n"(N) : "memory");
}
__device__ __forceinline__ uint32_t smem_u32(const void* p) {
    return (uint32_t)__cvta_generic_to_shared(p);
}

// ---------------- router (fused with x -> fp16 conversion) ----------------
__global__ void router_kernel(const float* __restrict__ x, const float* __restrict__ wr) {
    __shared__ float s_z[8];
    __shared__ float s_p[8][NEXP];
    int warp = threadIdx.x >> 5, lane = threadIdx.x & 31;
    int t = blockIdx.x * 8 + warp;
    const float* xr = x + (size_t)t * HDIM;
    __half* xh = g_Xh + (size_t)t * HDIM;
    float acc[NEXP];
#pragma unroll
    for (int e = 0; e < NEXP; e++) acc[e] = 0.f;
    for (int i = lane; i < HDIM; i += 32) {
        float xv = xr[i];
        xh[i] = __float2half_rn(xv);
        const float4* w4 = reinterpret_cast<const float4*>(wr + (size_t)i * NEXP);
        float4 w0 = w4[0], w1 = w4[1];
        acc[0] += xv * w0.x; acc[1] += xv * w0.y; acc[2] += xv * w0.z; acc[3] += xv * w0.w;
        acc[4] += xv * w1.x; acc[5] += xv * w1.y; acc[6] += xv * w1.z; acc[7] += xv * w1.w;
    }
#pragma unroll
    for (int e = 0; e < NEXP; e++)
#pragma unroll
        for (int o = 16; o > 0; o >>= 1) acc[e] += __shfl_xor_sync(0xffffffffu, acc[e], o);

    if (lane == 0) {
        float z = 0.f, mx = acc[0];
#pragma unroll
        for (int e = 0; e < NEXP; e++) { z += acc[e] * acc[e]; mx = fmaxf(mx, acc[e]); }
        float p[NEXP], s = 0.f;
#pragma unroll
        for (int e = 0; e < NEXP; e++) { p[e] = expf(acc[e] - mx); s += p[e]; }
        float inv = 1.f / s;
#pragma unroll
        for (int e = 0; e < NEXP; e++) p[e] *= inv;
        int i0 = 0;
#pragma unroll
        for (int e = 1; e < NEXP; e++) if (p[e] > p[i0]) i0 = e;
        int i1 = (i0 == 0) ? 1 : 0;
#pragma unroll
        for (int e = 0; e < NEXP; e++) if (e != i0 && p[e] > p[i1]) i1 = e;
        float s0 = p[i0], s1 = p[i1], sn = 1.f / (s0 + s1);
        g_eidx[t*2] = i0;  g_eidx[t*2+1] = i1;
        g_score[t*2] = s0 * sn; g_score[t*2+1] = s1 * sn;
        s_z[warp] = z;
#pragma unroll
        for (int e = 0; e < NEXP; e++) s_p[warp][e] = p[e];
    }
    __syncthreads();
    if (threadIdx.x == 0) {
        float z = 0.f;
#pragma unroll
        for (int w = 0; w < 8; w++) z += s_z[w];
        g_zpart[blockIdx.x] = z;
    }
    if (threadIdx.x < NEXP) {
        float ps = 0.f;
#pragma unroll
        for (int w = 0; w < 8; w++) ps += s_p[w][threadIdx.x];
        g_ppart[blockIdx.x * NEXP + threadIdx.x] = ps;
    }
}

// ---------------- fused count + scan + scatter (single block) ----------------
__global__ void route_kernel() {
    __shared__ int s_cnt[NEXP];
    __shared__ int s_cur[NEXP];
    int tid = threadIdx.x;                 // 1024 threads
    if (tid < NEXP) s_cnt[tid] = 0;
    __syncthreads();
    for (int i = tid; i < TOKENS*2; i += 1024)
        atomicAdd(&s_cnt[g_eidx[i]], 1);
    __syncthreads();
    if (tid == 0) {
        int o = 0;
        for (int e = 0; e < NEXP; e++) { g_offsets[e] = o; s_cur[e] = o; o += s_cnt[e]; }
        g_offsets[NEXP] = o;
    }
    __syncthreads();
    for (int i = tid; i < TOKENS*2; i += 1024) {
        int e = g_eidx[i];
        int pos = atomicAdd(&s_cur[e], 1);
        g_perm[pos] = i >> 1;
        g_slot_of[i] = pos;
    }
}

// ---------------- convert + transpose all 3 weights to fp16 [e][n][k] --------------
// grid: (2048, 1, 24); z: 0-7 gate, 8-15 up, 16-23 down. Tile 64(r) x 32(c).
__global__ void convert_w_kernel(const float* __restrict__ w_gate,
                                 const float* __restrict__ w_up,
                                 const float* __restrict__ w_down) {
    __shared__ float tile[64][33];
    const int kind = blockIdx.z >> 3;
    const int e = blockIdx.z & 7;
    const int R = (kind < 2) ? HDIM : FFDIM;
    const int C = (kind < 2) ? FFDIM : HDIM;
    const int tilesC = C / 32;
    const int tr = blockIdx.x / tilesC, tc = blockIdx.x % tilesC;
    const int r0 = tr * 64, c0 = tc * 32;
    const float* src = ((kind == 0) ? w_gate : (kind == 1) ? w_up : w_down) + (size_t)e * R * C;
    __half2* dst = reinterpret_cast<__half2*>(
        ((kind == 0) ? g_WgT : (kind == 1) ? g_WuT : g_WdT) + (size_t)e * R * C);

    const int tx = threadIdx.x, ty = threadIdx.y;   // (32, 8)
#pragma unroll
    for (int i = ty; i < 64; i += 8)
        tile[i][tx] = src[(size_t)(r0 + i) * C + c0 + tx];
    __syncthreads();
#pragma unroll
    for (int i = ty; i < 32; i += 8) {
        int c = c0 + i;
        __half2 v = __floats2half2_rn(tile[2*tx][i], tile[2*tx + 1][i]);
        dst[((size_t)c * R + r0) / 2 + tx] = v;
    }
}

// =======================================================================================
// GEMM1 (fp16): H[slot,:] = silu(X@Wg) * (X@Wu)
// BM=128, BN=64/matrix, BK=32. 256 threads, warps 2Mx4N, warp tile 64x16/matrix.
// smem (u32=half2): A 128x20, Bg 64x20, Bu 64x20 per stage; 3 stages.
// =======================================================================================
#define G1_A (128*20)
#define G1_B (64*20)
#define G1_STG (G1_A + 2*G1_B)          // 5120 u32 = 20480 B
#define G1_SMEM (3 * G1_STG * 4)        // 61440 B
__global__ __launch_bounds__(256) void gemm1_kernel() {
    const int e = blockIdx.z;
    const int off = g_offsets[e];
    const int cnt = g_offsets[e+1] - off;
    const int m0 = blockIdx.y * 128;
    if (m0 >= cnt) return;
    const int n0 = blockIdx.x * 64;

    extern __shared__ uint32_t smem[];

    const int tid = threadIdx.x, lane = tid & 31, wid = tid >> 5;
    const int wm = (wid & 1) * 64, wn = (wid >> 1) * 16;

    // A: 128 rows x 4 chunks(16B) = 512 -> 2/thread
    const __half* aptr[2]; int avalid[2]; uint32_t a_dst[2];
#pragma unroll
    for (int i = 0; i < 2; i++) {
        int q = tid + i * 256;
        int r = q >> 2, c4 = q & 3;
        int m = m0 + r;
        avalid[i] = (m < cnt) ? 16 : 0;
        aptr[i] = (m < cnt) ? (g_Xh + (size_t)g_perm[off + m] * HDIM + c4 * 8) : g_Xh;
        a_dst[i] = smem_u32(&smem[r*20 + c4*4]);
    }
    // B: 64 rows x 4 chunks per matrix = 256 -> 1/thread each
    const int brow = tid >> 2, bc4 = tid & 3;
    const __half* gptr = g_WgT + ((size_t)e * FFDIM + n0 + brow) * HDIM + bc4 * 8;
    const __half* uptr = g_WuT + ((size_t)e * FFDIM + n0 + brow) * HDIM + bc4 * 8;
    const uint32_t g_dst = smem_u32(&smem[G1_A + brow*20 + bc4*4]);
    const uint32_t u_dst = smem_u32(&smem[G1_A + G1_B + brow*20 + bc4*4]);

    float cg[4][2][4], cu[4][2][4];
#pragma unroll
    for (int mi = 0; mi < 4; mi++)
#pragma unroll
        for (int ni = 0; ni < 2; ni++)
#pragma unroll
            for (int j = 0; j < 4; j++) { cg[mi][ni][j] = 0.f; cu[mi][ni][j] = 0.f; }

    const int NSTEP = HDIM / 32;   // 32

#pragma unroll
    for (int p = 0; p < 2; p++) {
        const uint32_t so = p * G1_STG * 4;
        const int k0 = p * 32;
#pragma unroll
        for (int i = 0; i < 2; i++) cpa16(a_dst[i] + so, aptr[i] + k0, avalid[i]);
        cpa16(g_dst + so, gptr + k0, 16);
        cpa16(u_dst + so, uptr + k0, 16);
        cpa_commit();
    }

    int cur = 0;
    for (int s = 0; s < NSTEP; s++) {
        if (s + 1 < NSTEP) cpa_wait<1>(); else cpa_wait<0>();
        __syncthreads();

        const uint32_t* A  = smem + cur * G1_STG;
        const uint32_t* BG = A + G1_A;
        const uint32_t* BU = BG + G1_B;
        const int fr = lane >> 2, fc = lane & 3;

#pragma unroll
        for (int kk = 0; kk < 2; kk++) {
            uint32_t a[4][4];
#pragma unroll
            for (int mi = 0; mi < 4; mi++) {
                int rb = wm + mi * 16;
                a[mi][0] = A[(rb+fr  )*20 + kk*8 + fc    ];
                a[mi][1] = A[(rb+fr+8)*20 + kk*8 + fc    ];
                a[mi][2] = A[(rb+fr  )*20 + kk*8 + fc + 4];
                a[mi][3] = A[(rb+fr+8)*20 + kk*8 + fc + 4];
            }
            uint32_t bg[2][2], bu[2][2];
#pragma unroll
            for (int ni = 0; ni < 2; ni++) {
                int n = wn + ni * 8 + fr;
                bg[ni][0] = BG[n*20 + kk*8 + fc];
                bg[ni][1] = BG[n*20 + kk*8 + fc + 4];
                bu[ni][0] = BU[n*20 + kk*8 + fc];
                bu[ni][1] = BU[n*20 + kk*8 + fc + 4];
            }
#pragma unroll
            for (int mi = 0; mi < 4; mi++)
#pragma unroll
                for (int ni = 0; ni < 2; ni++) {
                    mma_f16(cg[mi][ni], a[mi], bg[ni]);
                    mma_f16(cu[mi][ni], a[mi], bu[ni]);
                }
        }
        __syncthreads();

        if (s + 2 < NSTEP) {
            const int nxt = (s + 2) % 3;
            const uint32_t so = nxt * G1_STG * 4;
            const int k0 = (s + 2) * 32;
#pragma unroll
            for (int i = 0; i < 2; i++) cpa16(a_dst[i] + so, aptr[i] + k0, avalid[i]);
            cpa16(g_dst + so, gptr + k0, 16);
            cpa16(u_dst + so, uptr + k0, 16);
        }
        cpa_commit();
        cur = (cur + 1) % 3;
    }

    // epilogue: silu(g)*u -> fp16 H
    const int fr = lane >> 2, fc2 = (lane & 3) * 2;
    __half2* H2 = reinterpret_cast<__half2*>(g_Hh);
#pragma unroll
    for (int mi = 0; mi < 4; mi++) {
        int r1 = wm + mi * 16 + fr;
        int m1 = m0 + r1, m2 = m1 + 8;
#pragma unroll
        for (int ni = 0; ni < 2; ni++) {
            int col = n0 + wn + ni * 8 + fc2;
            if (m1 < cnt) {
                float g0 = cg[mi][ni][0], g1 = cg[mi][ni][1];
                float u0 = cu[mi][ni][0], u1 = cu[mi][ni][1];
                float h0 = g0 / (1.f + expf(-g0)) * u0;
                float h1 = g1 / (1.f + expf(-g1)) * u1;
                H2[((size_t)(off+m1) * FFDIM + col) / 2] = __floats2half2_rn(h0, h1);
            }
            if (m2 < cnt) {
                float g0 = cg[mi][ni][2], g1 = cg[mi][ni][3];
                float u0 = cu[mi][ni][2], u1 = cu[mi][ni][3];
                float h0 = g0 / (1.f + expf(-g0)) * u0;
                float h1 = g1 / (1.f + expf(-g1)) * u1;
                H2[((size_t)(off+m2) * FFDIM + col) / 2] = __floats2half2_rn(h0, h1);
            }
        }
    }
}

// =======================================================================================
// GEMM2 (fp16): O[slot,:] = H @ Wd^T-layout
// BM=128, BN=128, BK=32. 256 threads, warps 2Mx4N, warp tile 64x32.
// smem: A 128x20, B 128x20 per stage; 3 stages.
// =======================================================================================
#define G2_A (128*20)
#define G2_B (128*20)
#define G2_STG (G2_A + G2_B)            // 5120 u32 = 20480 B
#define G2_SMEM (3 * G2_STG * 4)        // 61440 B
__global__ __launch_bounds__(256) void gemm2_kernel() {
    const int e = blockIdx.z;
    const int off = g_offsets[e];
    const int cnt = g_offsets[e+1] - off;
    const int m0 = blockIdx.y * 128;
    if (m0 >= cnt) return;
    const int n0 = blockIdx.x * 128;

    extern __shared__ uint32_t smem[];

    const int tid = threadIdx.x, lane = tid & 31, wid = tid >> 5;
    const int wm = (wid & 1) * 64, wn = (wid >> 1) * 32;

    // A: 512 chunks -> 2/thread
    const __half* aptr[2]; int avalid[2]; uint32_t a_dst[2];
#pragma unroll
    for (int i = 0; i < 2; i++) {
        int q = tid + i * 256;
        int r = q >> 2, c4 = q & 3;
        int m = m0 + r;
        avalid[i] = (m < cnt) ? 16 : 0;
        aptr[i] = (m < cnt) ? (g_Hh + (size_t)(off + m) * FFDIM + c4 * 8) : g_Hh;
        a_dst[i] = smem_u32(&smem[r*20 + c4*4]);
    }
    // B: 512 chunks -> 2/thread
    const __half* bptr[2]; uint32_t b_dst[2];
#pragma unroll
    for (int i = 0; i < 2; i++) {
        int q = tid + i * 256;
        int r = q >> 2, c4 = q & 3;
        bptr[i] = g_WdT + ((size_t)e * HDIM + n0 + r) * FFDIM + c4 * 8;
        b_dst[i] = smem_u32(&smem[G2_A + r*20 + c4*4]);
    }

    float c[4][4][4];
#pragma unroll
    for (int mi = 0; mi < 4; mi++)
#pragma unroll
        for (int ni = 0; ni < 4; ni++)
#pragma unroll
            for (int j = 0; j < 4; j++) c[mi][ni][j] = 0.f;

    const int NSTEP = FFDIM / 32;  // 128

#pragma unroll
    for (int p = 0; p < 2; p++) {
        const uint32_t so = p * G2_STG * 4;
        const int k0 = p * 32;
#pragma unroll
        for (int i = 0; i < 2; i++) cpa16(a_dst[i] + so, aptr[i] + k0, avalid[i]);
#pragma unroll
        for (int i = 0; i < 2; i++) cpa16(b_dst[i] + so, bptr[i] + k0, 16);
        cpa_commit();
    }

    int cur = 0;
    for (int s = 0; s < NSTEP; s++) {
        if (s + 1 < NSTEP) cpa_wait<1>(); else cpa_wait<0>();
        __syncthreads();

        const uint32_t* A = smem + cur * G2_STG;
        const uint32_t* B = A + G2_A;
        const int fr = lane >> 2, fc = lane & 3;

#pragma unroll
        for (int kk = 0; kk < 2; kk++) {
            uint32_t a[4][4];
#pragma unroll
            for (int mi = 0; mi < 4; mi++) {
                int rb = wm + mi * 16;
                a[mi][0] = A[(rb+fr  )*20 + kk*8 + fc    ];
                a[mi][1] = A[(rb+fr+8)*20 + kk*8 + fc    ];
                a[mi][2] = A[(rb+fr  )*20 + kk*8 + fc + 4];
                a[mi][3] = A[(rb+fr+8)*20 + kk*8 + fc + 4];
            }
            uint32_t b[4][2];
#pragma unroll
            for (int ni = 0; ni < 4; ni++) {
                int n = wn + ni * 8 + fr;
                b[ni][0] = B[n*20 + kk*8 + fc];
                b[ni][1] = B[n*20 + kk*8 + fc + 4];
            }
#pragma unroll
            for (int mi = 0; mi < 4; mi++)
#pragma unroll
                for (int ni = 0; ni < 4; ni++)
                    mma_f16(c[mi][ni], a[mi], b[ni]);
        }
        __syncthreads();

        if (s + 2 < NSTEP) {
            const int nxt = (s + 2) % 3;
            const uint32_t so = nxt * G2_STG * 4;
            const int k0 = (s + 2) * 32;
#pragma unroll
            for (int i = 0; i < 2; i++) cpa16(a_dst[i] + so, aptr[i] + k0, avalid[i]);
#pragma unroll
            for (int i = 0; i < 2; i++) cpa16(b_dst[i] + so, bptr[i] + k0, 16);
        }
        cpa_commit();
        cur = (cur + 1) % 3;
    }

    const int fr = lane >> 2, fc2 = (lane & 3) * 2;
#pragma unroll
    for (int mi = 0; mi < 4; mi++) {
        int r1 = wm + mi * 16 + fr;
        int m1 = m0 + r1, m2 = m1 + 8;
#pragma unroll
        for (int ni = 0; ni < 4; ni++) {
            int col = n0 + wn + ni * 8 + fc2;
            if (m1 < cnt)
                *reinterpret_cast<float2*>(&g_O[(size_t)(off+m1) * HDIM + col]) =
                    make_float2(c[mi][ni][0], c[mi][ni][1]);
            if (m2 < cnt)
                *reinterpret_cast<float2*>(&g_O[(size_t)(off+m2) * HDIM + col]) =
                    make_float2(c[mi][ni][2], c[mi][ni][3]);
        }
    }
}

// ---------------- combine + losses ----------------
__global__ void combine_kernel(float* __restrict__ out) {
    int idx = blockIdx.x * blockDim.x + threadIdx.x;
    int t = idx >> 8;
    int c4 = idx & 255;
    if (t >= TOKENS) return;
    int s0 = g_slot_of[t*2], s1 = g_slot_of[t*2+1];
    float w0 = g_score[t*2], w1 = g_score[t*2+1];
    float4 a = *reinterpret_cast<const float4*>(&g_O[(size_t)s0 * HDIM + c4*4]);
    float4 b = *reinterpret_cast<const float4*>(&g_O[(size_t)s1 * HDIM + c4*4]);
    float4 o;
    o.x = w0*a.x + w1*b.x; o.y = w0*a.y + w1*b.y;
    o.z = w0*a.z + w1*b.z; o.w = w0*a.w + w1*b.w;
    *reinterpret_cast<float4*>(&out[(size_t)t * HDIM + c4*4]) = o;
}

__global__ void loss_kernel(float* __restrict__ out) {
    int lane = threadIdx.x;
    float z = 0.f, pe[NEXP];
#pragma unroll
    for (int e = 0; e < NEXP; e++) pe[e] = 0.f;
    for (int i = lane; i < RBLOCKS; i += 32) {
        z += g_zpart[i];
#pragma unroll
        for (int e = 0; e < NEXP; e++) pe[e] += g_ppart[i*NEXP + e];
    }
#pragma unroll
    for (int o = 16; o > 0; o >>= 1) {
        z += __shfl_xor_sync(0xffffffffu, z, o);
#pragma unroll
        for (int e = 0; e < NEXP; e++) pe[e] += __shfl_xor_sync(0xffffffffu, pe[e], o);
    }
    if (lane == 0) {
        float zl = (float)NEXP * (z / (float)((size_t)TOKENS * NEXP));
        float aux = 0.f;
#pragma unroll
        for (int e = 0; e < NEXP; e++) {
            float pm = pe[e] / (float)TOKENS;
            aux += pm * logf(pm + 1e-9f);
        }
        out[(size_t)TOKENS * HDIM    ] = zl;
        out[(size_t)TOKENS * HDIM + 1] = (float)NEXP * aux;
    }
}

// ---------------- launch ----------------
extern "C" void kernel_launch(void* const* d_in, const int* in_sizes, int n_in,
                              void* d_out, int out_size) {
    const float* x        = (const float*)d_in[0];
    const float* w_router = (const float*)d_in[1];
    const float* w_gate   = (const float*)d_in[2];
    const float* w_up     = (const float*)d_in[3];
    const float* w_down   = (const float*)d_in[4];
    float* out = (float*)d_out;

    cudaFuncSetAttribute(gemm1_kernel, cudaFuncAttributeMaxDynamicSharedMemorySize, G1_SMEM);
    cudaFuncSetAttribute(gemm2_kernel, cudaFuncAttributeMaxDynamicSharedMemorySize, G2_SMEM);

    router_kernel<<<RBLOCKS, 256>>>(x, w_router);                               // 1
    route_kernel<<<1, 1024>>>();                                                // 2
    convert_w_kernel<<<dim3(2048, 1, 24), dim3(32, 8)>>>(w_gate, w_up, w_down); // 3
    gemm1_kernel<<<dim3(FFDIM/64, 64, NEXP), 256, G1_SMEM>>>();                 // 4 <- profiled
    gemm2_kernel<<<dim3(HDIM/128, 64, NEXP), 256, G2_SMEM>>>();                 // 5
    combine_kernel<<<(TOKENS*256)/256, 256>>>(out);                             // 6
    loss_kernel<<<1, 32>>>(out);                                                // 7
}

// round 9
// speedup vs baseline: 1.8615x; 1.0699x over previous
#include <cuda_runtime.h>
#include <cuda_fp16.h>
#include <cstdint>
#include <cstddef>

#define TOKENS 8192
#define HDIM 1024
#define FFDIM 4096
#define NEXP 8
#define SLOTS (TOKENS*2)
#define RBLOCKS (TOKENS/8)

// ---------------- scratch (device globals; no allocation allowed) ----------------
__device__ __half g_Xh[(size_t)TOKENS * HDIM];          // 16 MB  fp16 x
__device__ __half g_WgT[(size_t)NEXP * FFDIM * HDIM];   // 64 MB  w_gate^T [e][ff][h] fp16
__device__ __half g_WuT[(size_t)NEXP * FFDIM * HDIM];   // 64 MB  w_up^T
__device__ __half g_WdT[(size_t)NEXP * HDIM * FFDIM];   // 64 MB  w_down^T [e][h][ff]
__device__ __half g_Hh[(size_t)SLOTS * FFDIM];          // 128 MB fp16 silu(gate)*up
__device__ float  g_O[(size_t)SLOTS * HDIM];            // 64 MB  per-slot output (fp32)
__device__ int    g_perm[SLOTS];
__device__ int    g_slot_of[TOKENS*2];
__device__ float  g_score[TOKENS*2];
__device__ int    g_eidx[TOKENS*2];
__device__ int    g_offsets[NEXP+1];
__device__ float  g_zpart[RBLOCKS];
__device__ float  g_ppart[RBLOCKS*NEXP];

// ---------------- helpers ----------------
__device__ __forceinline__ void mma_f16(float c[4], const uint32_t a[4], const uint32_t b0,
                                        const uint32_t b1) {
    asm volatile(
        "mma.sync.aligned.m16n8k16.row.col.f32.f16.f16.f32 "
        "{%0,%1,%2,%3}, {%4,%5,%6,%7}, {%8,%9}, {%0,%1,%2,%3};\n"
        : "+f"(c[0]), "+f"(c[1]), "+f"(c[2]), "+f"(c[3])
        : "r"(a[0]), "r"(a[1]), "r"(a[2]), "r"(a[3]), "r"(b0), "r"(b1));
}
__device__ __forceinline__ void ldsm4(uint32_t r[4], uint32_t addr) {
    asm volatile("ldmatrix.sync.aligned.m8n8.x4.shared.b16 {%0,%1,%2,%3}, [%4];"
                 : "=r"(r[0]), "=r"(r[1]), "=r"(r[2]), "=r"(r[3]) : "r"(addr));
}
__device__ __forceinline__ void cpa16(uint32_t saddr, const void* gsrc, int srcbytes) {
    asm volatile("cp.async.cg.shared.global [%0], [%1], 16, %2;\n"
                 :: "r"(saddr), "l"(gsrc), "r"(srcbytes));
}
__device__ __forceinline__ void cpa_commit() {
    asm volatile("cp.async.commit_group;\n" ::: "memory");
}
template <int N>
__device__ __forceinline__ void cpa_wait() {
    asm volatile("cp.async.wait_group %0;\n" :: "n"(N) : "memory");
}
__device__ __forceinline__ uint32_t smem_u32(const void* p) {
    return (uint32_t)__cvta_generic_to_shared(p);
}

// ---------------- router (fused with x -> fp16 conversion) ----------------
__global__ void router_kernel(const float* __restrict__ x, const float* __restrict__ wr) {
    __shared__ float s_z[8];
    __shared__ float s_p[8][NEXP];
    int warp = threadIdx.x >> 5, lane = threadIdx.x & 31;
    int t = blockIdx.x * 8 + warp;
    const float* xr = x + (size_t)t * HDIM;
    __half* xh = g_Xh + (size_t)t * HDIM;
    float acc[NEXP];
#pragma unroll
    for (int e = 0; e < NEXP; e++) acc[e] = 0.f;
    for (int i = lane; i < HDIM; i += 32) {
        float xv = xr[i];
        xh[i] = __float2half_rn(xv);
        const float4* w4 = reinterpret_cast<const float4*>(wr + (size_t)i * NEXP);
        float4 w0 = w4[0], w1 = w4[1];
        acc[0] += xv * w0.x; acc[1] += xv * w0.y; acc[2] += xv * w0.z; acc[3] += xv * w0.w;
        acc[4] += xv * w1.x; acc[5] += xv * w1.y; acc[6] += xv * w1.z; acc[7] += xv * w1.w;
    }
#pragma unroll
    for (int e = 0; e < NEXP; e++)
#pragma unroll
        for (int o = 16; o > 0; o >>= 1) acc[e] += __shfl_xor_sync(0xffffffffu, acc[e], o);

    if (lane == 0) {
        float z = 0.f, mx = acc[0];
#pragma unroll
        for (int e = 0; e < NEXP; e++) { z += acc[e] * acc[e]; mx = fmaxf(mx, acc[e]); }
        float p[NEXP], s = 0.f;
#pragma unroll
        for (int e = 0; e < NEXP; e++) { p[e] = expf(acc[e] - mx); s += p[e]; }
        float inv = 1.f / s;
#pragma unroll
        for (int e = 0; e < NEXP; e++) p[e] *= inv;
        int i0 = 0;
#pragma unroll
        for (int e = 1; e < NEXP; e++) if (p[e] > p[i0]) i0 = e;
        int i1 = (i0 == 0) ? 1 : 0;
#pragma unroll
        for (int e = 0; e < NEXP; e++) if (e != i0 && p[e] > p[i1]) i1 = e;
        float s0 = p[i0], s1 = p[i1], sn = 1.f / (s0 + s1);
        g_eidx[t*2] = i0;  g_eidx[t*2+1] = i1;
        g_score[t*2] = s0 * sn; g_score[t*2+1] = s1 * sn;
        s_z[warp] = z;
#pragma unroll
        for (int e = 0; e < NEXP; e++) s_p[warp][e] = p[e];
    }
    __syncthreads();
    if (threadIdx.x == 0) {
        float z = 0.f;
#pragma unroll
        for (int w = 0; w < 8; w++) z += s_z[w];
        g_zpart[blockIdx.x] = z;
    }
    if (threadIdx.x < NEXP) {
        float ps = 0.f;
#pragma unroll
        for (int w = 0; w < 8; w++) ps += s_p[w][threadIdx.x];
        g_ppart[blockIdx.x * NEXP + threadIdx.x] = ps;
    }
}

// ---------------- fused count + scan + scatter (single block) ----------------
__global__ void route_kernel() {
    __shared__ int s_cnt[NEXP];
    __shared__ int s_cur[NEXP];
    int tid = threadIdx.x;                 // 1024 threads
    if (tid < NEXP) s_cnt[tid] = 0;
    __syncthreads();
    for (int i = tid; i < TOKENS*2; i += 1024)
        atomicAdd(&s_cnt[g_eidx[i]], 1);
    __syncthreads();
    if (tid == 0) {
        int o = 0;
        for (int e = 0; e < NEXP; e++) { g_offsets[e] = o; s_cur[e] = o; o += s_cnt[e]; }
        g_offsets[NEXP] = o;
    }
    __syncthreads();
    for (int i = tid; i < TOKENS*2; i += 1024) {
        int e = g_eidx[i];
        int pos = atomicAdd(&s_cur[e], 1);
        g_perm[pos] = i >> 1;
        g_slot_of[i] = pos;
    }
}

// ---------------- convert + transpose all 3 weights to fp16 [e][n][k] --------------
__global__ void convert_w_kernel(const float* __restrict__ w_gate,
                                 const float* __restrict__ w_up,
                                 const float* __restrict__ w_down) {
    __shared__ float tile[64][33];
    const int kind = blockIdx.z >> 3;
    const int e = blockIdx.z & 7;
    const int R = (kind < 2) ? HDIM : FFDIM;
    const int C = (kind < 2) ? FFDIM : HDIM;
    const int tilesC = C / 32;
    const int tr = blockIdx.x / tilesC, tc = blockIdx.x % tilesC;
    const int r0 = tr * 64, c0 = tc * 32;
    const float* src = ((kind == 0) ? w_gate : (kind == 1) ? w_up : w_down) + (size_t)e * R * C;
    __half2* dst = reinterpret_cast<__half2*>(
        ((kind == 0) ? g_WgT : (kind == 1) ? g_WuT : g_WdT) + (size_t)e * R * C);

    const int tx = threadIdx.x, ty = threadIdx.y;   // (32, 8)
#pragma unroll
    for (int i = ty; i < 64; i += 8)
        tile[i][tx] = src[(size_t)(r0 + i) * C + c0 + tx];
    __syncthreads();
#pragma unroll
    for (int i = ty; i < 32; i += 8) {
        int c = c0 + i;
        __half2 v = __floats2half2_rn(tile[2*tx][i], tile[2*tx + 1][i]);
        dst[((size_t)c * R + r0) / 2 + tx] = v;
    }
}

// =======================================================================================
// GEMM1 (fp16 + ldmatrix): H[slot,:] = silu(X@Wg) * (X@Wu)
// BM=128, BN=64/matrix, BK=32. 256 threads, warps 2Mx4N, warp tile 64x16/matrix.
// smem (u32=half2): A 128x20, Bg 64x20, Bu 64x20 per stage; 3 stages.
// =======================================================================================
#define G1_A (128*20)
#define G1_B (64*20)
#define G1_STG (G1_A + 2*G1_B)          // 5120 u32 = 20480 B
#define G1_SMEM (3 * G1_STG * 4)        // 61440 B
__global__ __launch_bounds__(256) void gemm1_kernel() {
    const int e = blockIdx.z;
    const int off = g_offsets[e];
    const int cnt = g_offsets[e+1] - off;
    const int m0 = blockIdx.y * 128;
    if (m0 >= cnt) return;
    const int n0 = blockIdx.x * 64;

    extern __shared__ uint32_t smem[];
    const uint32_t sb0 = smem_u32(smem);

    const int tid = threadIdx.x, lane = tid & 31, wid = tid >> 5;
    const int wm = (wid & 1) * 64, wn = (wid >> 1) * 16;

    // ldmatrix per-lane fragment addresses (byte offsets within a stage)
    const uint32_t afrag = sb0 + ((wm + (lane & 15)) * 20 + ((lane >> 4) << 2)) * 4;
    const int bfrow = ((lane >> 4) << 3) + (lane & 7);
    const uint32_t bfcol = ((lane >> 3) & 1) << 2;
    const uint32_t gfrag = sb0 + (G1_A + (wn + bfrow) * 20 + bfcol) * 4;
    const uint32_t ufrag = gfrag + G1_B * 4;

    // cp.async mappings
    const __half* aptr[2]; int avalid[2]; uint32_t a_dst[2];
#pragma unroll
    for (int i = 0; i < 2; i++) {
        int q = tid + i * 256;
        int r = q >> 2, c4 = q & 3;
        int m = m0 + r;
        avalid[i] = (m < cnt) ? 16 : 0;
        aptr[i] = (m < cnt) ? (g_Xh + (size_t)g_perm[off + m] * HDIM + c4 * 8) : g_Xh;
        a_dst[i] = sb0 + (r*20 + c4*4) * 4;
    }
    const int brow = tid >> 2, bc4 = tid & 3;
    const __half* gptr = g_WgT + ((size_t)e * FFDIM + n0 + brow) * HDIM + bc4 * 8;
    const __half* uptr = g_WuT + ((size_t)e * FFDIM + n0 + brow) * HDIM + bc4 * 8;
    const uint32_t g_dst = sb0 + (G1_A + brow*20 + bc4*4) * 4;
    const uint32_t u_dst = sb0 + (G1_A + G1_B + brow*20 + bc4*4) * 4;

    float cg[4][2][4], cu[4][2][4];
#pragma unroll
    for (int mi = 0; mi < 4; mi++)
#pragma unroll
        for (int ni = 0; ni < 2; ni++)
#pragma unroll
            for (int j = 0; j < 4; j++) { cg[mi][ni][j] = 0.f; cu[mi][ni][j] = 0.f; }

    const int NSTEP = HDIM / 32;   // 32

#pragma unroll
    for (int p = 0; p < 2; p++) {
        const uint32_t so = p * G1_STG * 4;
        const int k0 = p * 32;
#pragma unroll
        for (int i = 0; i < 2; i++) cpa16(a_dst[i] + so, aptr[i] + k0, avalid[i]);
        cpa16(g_dst + so, gptr + k0, 16);
        cpa16(u_dst + so, uptr + k0, 16);
        cpa_commit();
    }

    int cur = 0;
    for (int s = 0; s < NSTEP; s++) {
        if (s + 1 < NSTEP) cpa_wait<1>(); else cpa_wait<0>();
        __syncthreads();

        const uint32_t so = cur * G1_STG * 4;
#pragma unroll
        for (int kk = 0; kk < 2; kk++) {
            uint32_t a[4][4], bg[4], bu[4];
#pragma unroll
            for (int mi = 0; mi < 4; mi++)
                ldsm4(a[mi], afrag + so + mi * 1280 + kk * 32);   // 16 rows*20u32*4B =1280
            ldsm4(bg, gfrag + so + kk * 32);
            ldsm4(bu, ufrag + so + kk * 32);
#pragma unroll
            for (int mi = 0; mi < 4; mi++) {
                mma_f16(cg[mi][0], a[mi], bg[0], bg[1]);
                mma_f16(cg[mi][1], a[mi], bg[2], bg[3]);
                mma_f16(cu[mi][0], a[mi], bu[0], bu[1]);
                mma_f16(cu[mi][1], a[mi], bu[2], bu[3]);
            }
        }
        __syncthreads();

        if (s + 2 < NSTEP) {
            const uint32_t po = ((s + 2) % 3) * G1_STG * 4;
            const int k0 = (s + 2) * 32;
#pragma unroll
            for (int i = 0; i < 2; i++) cpa16(a_dst[i] + po, aptr[i] + k0, avalid[i]);
            cpa16(g_dst + po, gptr + k0, 16);
            cpa16(u_dst + po, uptr + k0, 16);
        }
        cpa_commit();
        cur = (cur + 1) % 3;
    }

    // epilogue: silu(g)*u -> fp16 H
    const int fr = lane >> 2, fc2 = (lane & 3) * 2;
    __half2* H2 = reinterpret_cast<__half2*>(g_Hh);
#pragma unroll
    for (int mi = 0; mi < 4; mi++) {
        int r1 = wm + mi * 16 + fr;
        int m1 = m0 + r1, m2 = m1 + 8;
#pragma unroll
        for (int ni = 0; ni < 2; ni++) {
            int col = n0 + wn + ni * 8 + fc2;
            if (m1 < cnt) {
                float g0 = cg[mi][ni][0], g1 = cg[mi][ni][1];
                float u0 = cu[mi][ni][0], u1 = cu[mi][ni][1];
                float h0 = g0 / (1.f + expf(-g0)) * u0;
                float h1 = g1 / (1.f + expf(-g1)) * u1;
                H2[((size_t)(off+m1) * FFDIM + col) / 2] = __floats2half2_rn(h0, h1);
            }
            if (m2 < cnt) {
                float g0 = cg[mi][ni][2], g1 = cg[mi][ni][3];
                float u0 = cu[mi][ni][2], u1 = cu[mi][ni][3];
                float h0 = g0 / (1.f + expf(-g0)) * u0;
                float h1 = g1 / (1.f + expf(-g1)) * u1;
                H2[((size_t)(off+m2) * FFDIM + col) / 2] = __floats2half2_rn(h0, h1);
            }
        }
    }
}

// =======================================================================================
// GEMM2 (fp16 + ldmatrix): O[slot,:] = H @ Wd^T-layout
// BM=128, BN=128, BK=32. 256 threads, warps 2Mx4N, warp tile 64x32.
// =======================================================================================
#define G2_A (128*20)
#define G2_B (128*20)
#define G2_STG (G2_A + G2_B)            // 5120 u32 = 20480 B
#define G2_SMEM (3 * G2_STG * 4)        // 61440 B
__global__ __launch_bounds__(256) void gemm2_kernel() {
    const int e = blockIdx.z;
    const int off = g_offsets[e];
    const int cnt = g_offsets[e+1] - off;
    const int m0 = blockIdx.y * 128;
    if (m0 >= cnt) return;
    const int n0 = blockIdx.x * 128;

    extern __shared__ uint32_t smem[];
    const uint32_t sb0 = smem_u32(smem);

    const int tid = threadIdx.x, lane = tid & 31, wid = tid >> 5;
    const int wm = (wid & 1) * 64, wn = (wid >> 1) * 32;

    const uint32_t afrag = sb0 + ((wm + (lane & 15)) * 20 + ((lane >> 4) << 2)) * 4;
    const int bfrow = ((lane >> 4) << 3) + (lane & 7);
    const uint32_t bfcol = ((lane >> 3) & 1) << 2;
    const uint32_t bfrag = sb0 + (G2_A + (wn + bfrow) * 20 + bfcol) * 4;

    const __half* aptr[2]; int avalid[2]; uint32_t a_dst[2];
#pragma unroll
    for (int i = 0; i < 2; i++) {
        int q = tid + i * 256;
        int r = q >> 2, c4 = q & 3;
        int m = m0 + r;
        avalid[i] = (m < cnt) ? 16 : 0;
        aptr[i] = (m < cnt) ? (g_Hh + (size_t)(off + m) * FFDIM + c4 * 8) : g_Hh;
        a_dst[i] = sb0 + (r*20 + c4*4) * 4;
    }
    const __half* bptr[2]; uint32_t b_dst[2];
#pragma unroll
    for (int i = 0; i < 2; i++) {
        int q = tid + i * 256;
        int r = q >> 2, c4 = q & 3;
        bptr[i] = g_WdT + ((size_t)e * HDIM + n0 + r) * FFDIM + c4 * 8;
        b_dst[i] = sb0 + (G2_A + r*20 + c4*4) * 4;
    }

    float c[4][4][4];
#pragma unroll
    for (int mi = 0; mi < 4; mi++)
#pragma unroll
        for (int ni = 0; ni < 4; ni++)
#pragma unroll
            for (int j = 0; j < 4; j++) c[mi][ni][j] = 0.f;

    const int NSTEP = FFDIM / 32;  // 128

#pragma unroll
    for (int p = 0; p < 2; p++) {
        const uint32_t so = p * G2_STG * 4;
        const int k0 = p * 32;
#pragma unroll
        for (int i = 0; i < 2; i++) cpa16(a_dst[i] + so, aptr[i] + k0, avalid[i]);
#pragma unroll
        for (int i = 0; i < 2; i++) cpa16(b_dst[i] + so, bptr[i] + k0, 16);
        cpa_commit();
    }

    int cur = 0;
    for (int s = 0; s < NSTEP; s++) {
        if (s + 1 < NSTEP) cpa_wait<1>(); else cpa_wait<0>();
        __syncthreads();

        const uint32_t so = cur * G2_STG * 4;
#pragma unroll
        for (int kk = 0; kk < 2; kk++) {
            uint32_t a[4][4], b[2][4];
#pragma unroll
            for (int mi = 0; mi < 4; mi++)
                ldsm4(a[mi], afrag + so + mi * 1280 + kk * 32);
            ldsm4(b[0], bfrag + so + kk * 32);                 // n-tiles 0,1
            ldsm4(b[1], bfrag + so + 16 * 80 + kk * 32);       // n-tiles 2,3 (+16 rows)
#pragma unroll
            for (int mi = 0; mi < 4; mi++) {
                mma_f16(c[mi][0], a[mi], b[0][0], b[0][1]);
                mma_f16(c[mi][1], a[mi], b[0][2], b[0][3]);
                mma_f16(c[mi][2], a[mi], b[1][0], b[1][1]);
                mma_f16(c[mi][3], a[mi], b[1][2], b[1][3]);
            }
        }
        __syncthreads();

        if (s + 2 < NSTEP) {
            const uint32_t po = ((s + 2) % 3) * G2_STG * 4;
            const int k0 = (s + 2) * 32;
#pragma unroll
            for (int i = 0; i < 2; i++) cpa16(a_dst[i] + po, aptr[i] + k0, avalid[i]);
#pragma unroll
            for (int i = 0; i < 2; i++) cpa16(b_dst[i] + po, bptr[i] + k0, 16);
        }
        cpa_commit();
        cur = (cur + 1) % 3;
    }

    const int fr = lane >> 2, fc2 = (lane & 3) * 2;
#pragma unroll
    for (int mi = 0; mi < 4; mi++) {
        int r1 = wm + mi * 16 + fr;
        int m1 = m0 + r1, m2 = m1 + 8;
#pragma unroll
        for (int ni = 0; ni < 4; ni++) {
            int col = n0 + wn + ni * 8 + fc2;
            if (m1 < cnt)
                *reinterpret_cast<float2*>(&g_O[(size_t)(off+m1) * HDIM + col]) =
                    make_float2(c[mi][ni][0], c[mi][ni][1]);
            if (m2 < cnt)
                *reinterpret_cast<float2*>(&g_O[(size_t)(off+m2) * HDIM + col]) =
                    make_float2(c[mi][ni][2], c[mi][ni][3]);
        }
    }
}

// ---------------- combine + losses ----------------
__global__ void combine_kernel(float* __restrict__ out) {
    int idx = blockIdx.x * blockDim.x + threadIdx.x;
    int t = idx >> 8;
    int c4 = idx & 255;
    if (t >= TOKENS) return;
    int s0 = g_slot_of[t*2], s1 = g_slot_of[t*2+1];
    float w0 = g_score[t*2], w1 = g_score[t*2+1];
    float4 a = *reinterpret_cast<const float4*>(&g_O[(size_t)s0 * HDIM + c4*4]);
    float4 b = *reinterpret_cast<const float4*>(&g_O[(size_t)s1 * HDIM + c4*4]);
    float4 o;
    o.x = w0*a.x + w1*b.x; o.y = w0*a.y + w1*b.y;
    o.z = w0*a.z + w1*b.z; o.w = w0*a.w + w1*b.w;
    *reinterpret_cast<float4*>(&out[(size_t)t * HDIM + c4*4]) = o;
}

__global__ void loss_kernel(float* __restrict__ out) {
    int lane = threadIdx.x;
    float z = 0.f, pe[NEXP];
#pragma unroll
    for (int e = 0; e < NEXP; e++) pe[e] = 0.f;
    for (int i = lane; i < RBLOCKS; i += 32) {
        z += g_zpart[i];
#pragma unroll
        for (int e = 0; e < NEXP; e++) pe[e] += g_ppart[i*NEXP + e];
    }
#pragma unroll
    for (int o = 16; o > 0; o >>= 1) {
        z += __shfl_xor_sync(0xffffffffu, z, o);
#pragma unroll
        for (int e = 0; e < NEXP; e++) pe[e] += __shfl_xor_sync(0xffffffffu, pe[e], o);
    }
    if (lane == 0) {
        float zl = (float)NEXP * (z / (float)((size_t)TOKENS * NEXP));
        float aux = 0.f;
#pragma unroll
        for (int e = 0; e < NEXP; e++) {
            float pm = pe[e] / (float)TOKENS;
            aux += pm * logf(pm + 1e-9f);
        }
        out[(size_t)TOKENS * HDIM    ] = zl;
        out[(size_t)TOKENS * HDIM + 1] = (float)NEXP * aux;
    }
}

// ---------------- launch ----------------
extern "C" void kernel_launch(void* const* d_in, const int* in_sizes, int n_in,
                              void* d_out, int out_size) {
    const float* x        = (const float*)d_in[0];
    const float* w_router = (const float*)d_in[1];
    const float* w_gate   = (const float*)d_in[2];
    const float* w_up     = (const float*)d_in[3];
    const float* w_down   = (const float*)d_in[4];
    float* out = (float*)d_out;

    cudaFuncSetAttribute(gemm1_kernel, cudaFuncAttributeMaxDynamicSharedMemorySize, G1_SMEM);
    cudaFuncSetAttribute(gemm2_kernel, cudaFuncAttributeMaxDynamicSharedMemorySize, G2_SMEM);

    router_kernel<<<RBLOCKS, 256>>>(x, w_router);                               // 1
    route_kernel<<<1, 1024>>>();                                                // 2
    convert_w_kernel<<<dim3(2048, 1, 24), dim3(32, 8)>>>(w_gate, w_up, w_down); // 3
    gemm1_kernel<<<dim3(FFDIM/64, 64, NEXP), 256, G1_SMEM>>>();                 // 4 <- profiled
    gemm2_kernel<<<dim3(HDIM/128, 64, NEXP), 256, G2_SMEM>>>();                 // 5
    combine_kernel<<<(TOKENS*256)/256, 256>>>(out);                             // 6
    loss_kernel<<<1, 32>>>(out);                                                // 7
}

// round 10
// speedup vs baseline: 2.2867x; 1.2284x over previous
#include <cuda_runtime.h>
#include <cuda_fp16.h>
#include <cstdint>
#include <cstddef>

#define TOKENS 8192
#define HDIM 1024
#define FFDIM 4096
#define NEXP 8
#define SLOTS (TOKENS*2)
#define RBLOCKS (TOKENS/8)

// ---------------- scratch (device globals; no allocation allowed) ----------------
__device__ __half g_Xh[(size_t)TOKENS * HDIM];          // 16 MB  fp16 x
__device__ __half g_WgT[(size_t)NEXP * FFDIM * HDIM];   // 64 MB  w_gate^T [e][ff][h] fp16
__device__ __half g_WuT[(size_t)NEXP * FFDIM * HDIM];   // 64 MB  w_up^T
__device__ __half g_WdT[(size_t)NEXP * HDIM * FFDIM];   // 64 MB  w_down^T [e][h][ff]
__device__ __half g_Hh[(size_t)SLOTS * FFDIM];          // 128 MB fp16 silu(gate)*up
__device__ float  g_O[(size_t)SLOTS * HDIM];            // 64 MB  per-slot output (fp32)
__device__ int    g_perm[SLOTS];
__device__ int    g_slot_of[TOKENS*2];
__device__ float  g_score[TOKENS*2];
__device__ int    g_eidx[TOKENS*2];
__device__ int    g_offsets[NEXP+1];
__device__ float  g_zpart[RBLOCKS];
__device__ float  g_ppart[RBLOCKS*NEXP];

// ---------------- helpers ----------------
__device__ __forceinline__ void mma_f16(float c[4], const uint32_t a[4], const uint32_t b0,
                                        const uint32_t b1) {
    asm volatile(
        "mma.sync.aligned.m16n8k16.row.col.f32.f16.f16.f32 "
        "{%0,%1,%2,%3}, {%4,%5,%6,%7}, {%8,%9}, {%0,%1,%2,%3};\n"
        : "+f"(c[0]), "+f"(c[1]), "+f"(c[2]), "+f"(c[3])
        : "r"(a[0]), "r"(a[1]), "r"(a[2]), "r"(a[3]), "r"(b0), "r"(b1));
}
__device__ __forceinline__ void ldsm4(uint32_t r[4], uint32_t addr) {
    asm volatile("ldmatrix.sync.aligned.m8n8.x4.shared.b16 {%0,%1,%2,%3}, [%4];"
                 : "=r"(r[0]), "=r"(r[1]), "=r"(r[2]), "=r"(r[3]) : "r"(addr));
}
__device__ __forceinline__ void cpa16(uint32_t saddr, const void* gsrc, int srcbytes) {
    asm volatile("cp.async.cg.shared.global [%0], [%1], 16, %2;\n"
                 :: "r"(saddr), "l"(gsrc), "r"(srcbytes));
}
__device__ __forceinline__ void cpa_commit() {
    asm volatile("cp.async.commit_group;\n" ::: "memory");
}
template <int N>
__device__ __forceinline__ void cpa_wait() {
    asm volatile("cp.async.wait_group %0;\n" :: "n"(N) : "memory");
}
__device__ __forceinline__ uint32_t smem_u32(const void* p) {
    return (uint32_t)__cvta_generic_to_shared(p);
}

// ---------------- router (fused with x -> fp16 conversion) ----------------
__global__ void router_kernel(const float* __restrict__ x, const float* __restrict__ wr) {
    __shared__ float s_z[8];
    __shared__ float s_p[8][NEXP];
    int warp = threadIdx.x >> 5, lane = threadIdx.x & 31;
    int t = blockIdx.x * 8 + warp;
    const float* xr = x + (size_t)t * HDIM;
    __half* xh = g_Xh + (size_t)t * HDIM;
    float acc[NEXP];
#pragma unroll
    for (int e = 0; e < NEXP; e++) acc[e] = 0.f;
    for (int i = lane; i < HDIM; i += 32) {
        float xv = xr[i];
        xh[i] = __float2half_rn(xv);
        const float4* w4 = reinterpret_cast<const float4*>(wr + (size_t)i * NEXP);
        float4 w0 = w4[0], w1 = w4[1];
        acc[0] += xv * w0.x; acc[1] += xv * w0.y; acc[2] += xv * w0.z; acc[3] += xv * w0.w;
        acc[4] += xv * w1.x; acc[5] += xv * w1.y; acc[6] += xv * w1.z; acc[7] += xv * w1.w;
    }
#pragma unroll
    for (int e = 0; e < NEXP; e++)
#pragma unroll
        for (int o = 16; o > 0; o >>= 1) acc[e] += __shfl_xor_sync(0xffffffffu, acc[e], o);

    if (lane == 0) {
        float z = 0.f, mx = acc[0];
#pragma unroll
        for (int e = 0; e < NEXP; e++) { z += acc[e] * acc[e]; mx = fmaxf(mx, acc[e]); }
        float p[NEXP], s = 0.f;
#pragma unroll
        for (int e = 0; e < NEXP; e++) { p[e] = expf(acc[e] - mx); s += p[e]; }
        float inv = 1.f / s;
#pragma unroll
        for (int e = 0; e < NEXP; e++) p[e] *= inv;
        int i0 = 0;
#pragma unroll
        for (int e = 1; e < NEXP; e++) if (p[e] > p[i0]) i0 = e;
        int i1 = (i0 == 0) ? 1 : 0;
#pragma unroll
        for (int e = 0; e < NEXP; e++) if (e != i0 && p[e] > p[i1]) i1 = e;
        float s0 = p[i0], s1 = p[i1], sn = 1.f / (s0 + s1);
        g_eidx[t*2] = i0;  g_eidx[t*2+1] = i1;
        g_score[t*2] = s0 * sn; g_score[t*2+1] = s1 * sn;
        s_z[warp] = z;
#pragma unroll
        for (int e = 0; e < NEXP; e++) s_p[warp][e] = p[e];
    }
    __syncthreads();
    if (threadIdx.x == 0) {
        float z = 0.f;
#pragma unroll
        for (int w = 0; w < 8; w++) z += s_z[w];
        g_zpart[blockIdx.x] = z;
    }
    if (threadIdx.x < NEXP) {
        float ps = 0.f;
#pragma unroll
        for (int w = 0; w < 8; w++) ps += s_p[w][threadIdx.x];
        g_ppart[blockIdx.x * NEXP + threadIdx.x] = ps;
    }
}

// ---------------- fused count + scan + scatter (single block) ----------------
__global__ void route_kernel() {
    __shared__ int s_cnt[NEXP];
    __shared__ int s_cur[NEXP];
    int tid = threadIdx.x;                 // 1024 threads
    if (tid < NEXP) s_cnt[tid] = 0;
    __syncthreads();
    for (int i = tid; i < TOKENS*2; i += 1024)
        atomicAdd(&s_cnt[g_eidx[i]], 1);
    __syncthreads();
    if (tid == 0) {
        int o = 0;
        for (int e = 0; e < NEXP; e++) { g_offsets[e] = o; s_cur[e] = o; o += s_cnt[e]; }
        g_offsets[NEXP] = o;
    }
    __syncthreads();
    for (int i = tid; i < TOKENS*2; i += 1024) {
        int e = g_eidx[i];
        int pos = atomicAdd(&s_cur[e], 1);
        g_perm[pos] = i >> 1;
        g_slot_of[i] = pos;
    }
}

// ---------------- convert + transpose all 3 weights to fp16 [e][n][k] --------------
__global__ void convert_w_kernel(const float* __restrict__ w_gate,
                                 const float* __restrict__ w_up,
                                 const float* __restrict__ w_down) {
    __shared__ float tile[64][33];
    const int kind = blockIdx.z >> 3;
    const int e = blockIdx.z & 7;
    const int R = (kind < 2) ? HDIM : FFDIM;
    const int C = (kind < 2) ? FFDIM : HDIM;
    const int tilesC = C / 32;
    const int tr = blockIdx.x / tilesC, tc = blockIdx.x % tilesC;
    const int r0 = tr * 64, c0 = tc * 32;
    const float* src = ((kind == 0) ? w_gate : (kind == 1) ? w_up : w_down) + (size_t)e * R * C;
    __half2* dst = reinterpret_cast<__half2*>(
        ((kind == 0) ? g_WgT : (kind == 1) ? g_WuT : g_WdT) + (size_t)e * R * C);

    const int tx = threadIdx.x, ty = threadIdx.y;   // (32, 8)
#pragma unroll
    for (int i = ty; i < 64; i += 8)
        tile[i][tx] = src[(size_t)(r0 + i) * C + c0 + tx];
    __syncthreads();
#pragma unroll
    for (int i = ty; i < 32; i += 8) {
        int c = c0 + i;
        __half2 v = __floats2half2_rn(tile[2*tx][i], tile[2*tx + 1][i]);
        dst[((size_t)c * R + r0) / 2 + tx] = v;
    }
}

// =======================================================================================
// GEMM1 (fp16 + ldmatrix + BK=64 + single barrier): H = silu(X@Wg) * (X@Wu)
// BM=128, BN=64/matrix, BK=64. 256 threads, warps 2Mx4N.
// smem rows: 128 halves data + 16B pad -> stride 36 u32 (ldmatrix conflict-free).
// Stage = A 128x36 + Bg 64x36 + Bu 64x36 = 9216 u32 = 36864 B; 3 stages = 110592 B.
// =======================================================================================
#define G1_A (128*36)
#define G1_B (64*36)
#define G1_STG (G1_A + 2*G1_B)          // 9216 u32
#define G1_SMEM (3 * G1_STG * 4)        // 110592 B
__global__ __launch_bounds__(256, 2) void gemm1_kernel() {
    const int e = blockIdx.z;
    const int off = g_offsets[e];
    const int cnt = g_offsets[e+1] - off;
    const int m0 = blockIdx.y * 128;
    if (m0 >= cnt) return;
    const int n0 = blockIdx.x * 64;

    extern __shared__ uint32_t smem[];
    const uint32_t sb0 = smem_u32(smem);

    const int tid = threadIdx.x, lane = tid & 31, wid = tid >> 5;
    const int wm = (wid & 1) * 64, wn = (wid >> 1) * 16;

    // ldmatrix fragment addresses (byte offsets within a stage)
    const uint32_t afrag = sb0 + ((wm + (lane & 15)) * 36 + ((lane >> 4) << 2)) * 4;
    const int bfrow = ((lane >> 4) << 3) + (lane & 7);
    const uint32_t bfcol = ((lane >> 3) & 1) << 2;
    const uint32_t gfrag = sb0 + (G1_A + (wn + bfrow) * 36 + bfcol) * 4;
    const uint32_t ufrag = gfrag + G1_B * 4;

    // cp.async: A 128 rows x 8 chunks = 1024 -> 4/thread; rows r = (tid>>3) + i*32
    const int ac = tid & 7;                      // 16B chunk within row
    const int ar = tid >> 3;                     // base row
    const __half* aptr[4]; int avalid[4];
#pragma unroll
    for (int i = 0; i < 4; i++) {
        int m = m0 + ar + i * 32;
        avalid[i] = (m < cnt) ? 16 : 0;
        aptr[i] = (m < cnt) ? (g_Xh + (size_t)g_perm[off + m] * HDIM + ac * 8) : g_Xh;
    }
    const uint32_t a_dst0 = sb0 + (ar*36 + ac*4) * 4;    // +i*32*144 B per i
    // B: 64 rows x 8 chunks = 512 -> 2/thread; rows r = (tid>>3) + i*32
    const __half* gptr = g_WgT + ((size_t)e * FFDIM + n0 + ar) * HDIM + ac * 8;
    const __half* uptr = g_WuT + ((size_t)e * FFDIM + n0 + ar) * HDIM + ac * 8;
    const uint32_t g_dst0 = sb0 + (G1_A + ar*36 + ac*4) * 4;
    const uint32_t u_dst0 = g_dst0 + G1_B * 4;

    float cg[4][2][4], cu[4][2][4];
#pragma unroll
    for (int mi = 0; mi < 4; mi++)
#pragma unroll
        for (int ni = 0; ni < 2; ni++)
#pragma unroll
            for (int j = 0; j < 4; j++) { cg[mi][ni][j] = 0.f; cu[mi][ni][j] = 0.f; }

    const int NSTEP = HDIM / 64;   // 16

#pragma unroll
    for (int p = 0; p < 2; p++) {
        const uint32_t so = p * G1_STG * 4;
        const int k0 = p * 64;
#pragma unroll
        for (int i = 0; i < 4; i++) cpa16(a_dst0 + i*4608 + so, aptr[i] + k0, avalid[i]);
#pragma unroll
        for (int i = 0; i < 2; i++) {
            cpa16(g_dst0 + i*4608 + so, gptr + (size_t)(i*32) * HDIM + k0, 16);
            cpa16(u_dst0 + i*4608 + so, uptr + (size_t)(i*32) * HDIM + k0, 16);
        }
        cpa_commit();
    }

    int cur = 0;
    for (int s = 0; s < NSTEP; s++) {
        if (s + 1 < NSTEP) cpa_wait<1>(); else cpa_wait<0>();
        __syncthreads();

        const uint32_t so = cur * G1_STG * 4;
#pragma unroll
        for (int kk = 0; kk < 4; kk++) {
            uint32_t a[4][4], bg[4], bu[4];
#pragma unroll
            for (int mi = 0; mi < 4; mi++)
                ldsm4(a[mi], afrag + so + mi * 2304 + kk * 32);   // 16 rows*36u32*4B = 2304
            ldsm4(bg, gfrag + so + kk * 32);
            ldsm4(bu, ufrag + so + kk * 32);
#pragma unroll
            for (int mi = 0; mi < 4; mi++) {
                mma_f16(cg[mi][0], a[mi], bg[0], bg[1]);
                mma_f16(cg[mi][1], a[mi], bg[2], bg[3]);
                mma_f16(cu[mi][0], a[mi], bu[0], bu[1]);
                mma_f16(cu[mi][1], a[mi], bu[2], bu[3]);
            }
        }
        // single barrier per step: prefetch target (s+2)%3 was last read at s-1,
        // which all threads finished before this iteration's __syncthreads.
        if (s + 2 < NSTEP) {
            const uint32_t po = ((s + 2) % 3) * G1_STG * 4;
            const int k0 = (s + 2) * 64;
#pragma unroll
            for (int i = 0; i < 4; i++) cpa16(a_dst0 + i*4608 + po, aptr[i] + k0, avalid[i]);
#pragma unroll
            for (int i = 0; i < 2; i++) {
                cpa16(g_dst0 + i*4608 + po, gptr + (size_t)(i*32) * HDIM + k0, 16);
                cpa16(u_dst0 + i*4608 + po, uptr + (size_t)(i*32) * HDIM + k0, 16);
            }
        }
        cpa_commit();
        cur = (cur + 1) % 3;
    }

    // epilogue: silu(g)*u -> fp16 H
    const int fr = lane >> 2, fc2 = (lane & 3) * 2;
    __half2* H2 = reinterpret_cast<__half2*>(g_Hh);
#pragma unroll
    for (int mi = 0; mi < 4; mi++) {
        int r1 = wm + mi * 16 + fr;
        int m1 = m0 + r1, m2 = m1 + 8;
#pragma unroll
        for (int ni = 0; ni < 2; ni++) {
            int col = n0 + wn + ni * 8 + fc2;
            if (m1 < cnt) {
                float g0 = cg[mi][ni][0], g1 = cg[mi][ni][1];
                float u0 = cu[mi][ni][0], u1 = cu[mi][ni][1];
                float h0 = g0 / (1.f + expf(-g0)) * u0;
                float h1 = g1 / (1.f + expf(-g1)) * u1;
                H2[((size_t)(off+m1) * FFDIM + col) / 2] = __floats2half2_rn(h0, h1);
            }
            if (m2 < cnt) {
                float g0 = cg[mi][ni][2], g1 = cg[mi][ni][3];
                float u0 = cu[mi][ni][2], u1 = cu[mi][ni][3];
                float h0 = g0 / (1.f + expf(-g0)) * u0;
                float h1 = g1 / (1.f + expf(-g1)) * u1;
                H2[((size_t)(off+m2) * FFDIM + col) / 2] = __floats2half2_rn(h0, h1);
            }
        }
    }
}

// =======================================================================================
// GEMM2 (fp16 + ldmatrix + BK=64 + single barrier): O = H @ Wd^T-layout
// BM=128, BN=128, BK=64. 256 threads, warps 2Mx4N.
// Stage = A 128x36 + B 128x36 = 9216 u32 = 36864 B; 3 stages.
// =======================================================================================
#define G2_A (128*36)
#define G2_B (128*36)
#define G2_STG (G2_A + G2_B)            // 9216 u32
#define G2_SMEM (3 * G2_STG * 4)        // 110592 B
__global__ __launch_bounds__(256, 2) void gemm2_kernel() {
    const int e = blockIdx.z;
    const int off = g_offsets[e];
    const int cnt = g_offsets[e+1] - off;
    const int m0 = blockIdx.y * 128;
    if (m0 >= cnt) return;
    const int n0 = blockIdx.x * 128;

    extern __shared__ uint32_t smem[];
    const uint32_t sb0 = smem_u32(smem);

    const int tid = threadIdx.x, lane = tid & 31, wid = tid >> 5;
    const int wm = (wid & 1) * 64, wn = (wid >> 1) * 32;

    const uint32_t afrag = sb0 + ((wm + (lane & 15)) * 36 + ((lane >> 4) << 2)) * 4;
    const int bfrow = ((lane >> 4) << 3) + (lane & 7);
    const uint32_t bfcol = ((lane >> 3) & 1) << 2;
    const uint32_t bfrag = sb0 + (G2_A + (wn + bfrow) * 36 + bfcol) * 4;

    const int ac = tid & 7;
    const int ar = tid >> 3;
    const __half* aptr[4]; int avalid[4];
#pragma unroll
    for (int i = 0; i < 4; i++) {
        int m = m0 + ar + i * 32;
        avalid[i] = (m < cnt) ? 16 : 0;
        aptr[i] = (m < cnt) ? (g_Hh + (size_t)(off + m) * FFDIM + ac * 8) : g_Hh;
    }
    const uint32_t a_dst0 = sb0 + (ar*36 + ac*4) * 4;
    const __half* bptr = g_WdT + ((size_t)e * HDIM + n0 + ar) * FFDIM + ac * 8;
    const uint32_t b_dst0 = sb0 + (G2_A + ar*36 + ac*4) * 4;

    float c[4][4][4];
#pragma unroll
    for (int mi = 0; mi < 4; mi++)
#pragma unroll
        for (int ni = 0; ni < 4; ni++)
#pragma unroll
            for (int j = 0; j < 4; j++) c[mi][ni][j] = 0.f;

    const int NSTEP = FFDIM / 64;  // 64

#pragma unroll
    for (int p = 0; p < 2; p++) {
        const uint32_t so = p * G2_STG * 4;
        const int k0 = p * 64;
#pragma unroll
        for (int i = 0; i < 4; i++) cpa16(a_dst0 + i*4608 + so, aptr[i] + k0, avalid[i]);
#pragma unroll
        for (int i = 0; i < 4; i++)
            cpa16(b_dst0 + i*4608 + so, bptr + (size_t)(i*32) * FFDIM + k0, 16);
        cpa_commit();
    }

    int cur = 0;
    for (int s = 0; s < NSTEP; s++) {
        if (s + 1 < NSTEP) cpa_wait<1>(); else cpa_wait<0>();
        __syncthreads();

        const uint32_t so = cur * G2_STG * 4;
#pragma unroll
        for (int kk = 0; kk < 4; kk++) {
            uint32_t a[4][4], b[2][4];
#pragma unroll
            for (int mi = 0; mi < 4; mi++)
                ldsm4(a[mi], afrag + so + mi * 2304 + kk * 32);
            ldsm4(b[0], bfrag + so + kk * 32);                 // n-tiles 0,1
            ldsm4(b[1], bfrag + so + 2304 + kk * 32);          // n-tiles 2,3 (+16 rows)
#pragma unroll
            for (int mi = 0; mi < 4; mi++) {
                mma_f16(c[mi][0], a[mi], b[0][0], b[0][1]);
                mma_f16(c[mi][1], a[mi], b[0][2], b[0][3]);
                mma_f16(c[mi][2], a[mi], b[1][0], b[1][1]);
                mma_f16(c[mi][3], a[mi], b[1][2], b[1][3]);
            }
        }
        if (s + 2 < NSTEP) {
            const uint32_t po = ((s + 2) % 3) * G2_STG * 4;
            const int k0 = (s + 2) * 64;
#pragma unroll
            for (int i = 0; i < 4; i++) cpa16(a_dst0 + i*4608 + po, aptr[i] + k0, avalid[i]);
#pragma unroll
            for (int i = 0; i < 4; i++)
                cpa16(b_dst0 + i*4608 + po, bptr + (size_t)(i*32) * FFDIM + k0, 16);
        }
        cpa_commit();
        cur = (cur + 1) % 3;
    }

    const int fr = lane >> 2, fc2 = (lane & 3) * 2;
#pragma unroll
    for (int mi = 0; mi < 4; mi++) {
        int r1 = wm + mi * 16 + fr;
        int m1 = m0 + r1, m2 = m1 + 8;
#pragma unroll
        for (int ni = 0; ni < 4; ni++) {
            int col = n0 + wn + ni * 8 + fc2;
            if (m1 < cnt)
                *reinterpret_cast<float2*>(&g_O[(size_t)(off+m1) * HDIM + col]) =
                    make_float2(c[mi][ni][0], c[mi][ni][1]);
            if (m2 < cnt)
                *reinterpret_cast<float2*>(&g_O[(size_t)(off+m2) * HDIM + col]) =
                    make_float2(c[mi][ni][2], c[mi][ni][3]);
        }
    }
}

// ---------------- combine + losses ----------------
__global__ void combine_kernel(float* __restrict__ out) {
    int idx = blockIdx.x * blockDim.x + threadIdx.x;
    int t = idx >> 8;
    int c4 = idx & 255;
    if (t >= TOKENS) return;
    int s0 = g_slot_of[t*2], s1 = g_slot_of[t*2+1];
    float w0 = g_score[t*2], w1 = g_score[t*2+1];
    float4 a = *reinterpret_cast<const float4*>(&g_O[(size_t)s0 * HDIM + c4*4]);
    float4 b = *reinterpret_cast<const float4*>(&g_O[(size_t)s1 * HDIM + c4*4]);
    float4 o;
    o.x = w0*a.x + w1*b.x; o.y = w0*a.y + w1*b.y;
    o.z = w0*a.z + w1*b.z; o.w = w0*a.w + w1*b.w;
    *reinterpret_cast<float4*>(&out[(size_t)t * HDIM + c4*4]) = o;
}

__global__ void loss_kernel(float* __restrict__ out) {
    int lane = threadIdx.x;
    float z = 0.f, pe[NEXP];
#pragma unroll
    for (int e = 0; e < NEXP; e++) pe[e] = 0.f;
    for (int i = lane; i < RBLOCKS; i += 32) {
        z += g_zpart[i];
#pragma unroll
        for (int e = 0; e < NEXP; e++) pe[e] += g_ppart[i*NEXP + e];
    }
#pragma unroll
    for (int o = 16; o > 0; o >>= 1) {
        z += __shfl_xor_sync(0xffffffffu, z, o);
#pragma unroll
        for (int e = 0; e < NEXP; e++) pe[e] += __shfl_xor_sync(0xffffffffu, pe[e], o);
    }
    if (lane == 0) {
        float zl = (float)NEXP * (z / (float)((size_t)TOKENS * NEXP));
        float aux = 0.f;
#pragma unroll
        for (int e = 0; e < NEXP; e++) {
            float pm = pe[e] / (float)TOKENS;
            aux += pm * logf(pm + 1e-9f);
        }
        out[(size_t)TOKENS * HDIM    ] = zl;
        out[(size_t)TOKENS * HDIM + 1] = (float)NEXP * aux;
    }
}

// ---------------- launch ----------------
extern "C" void kernel_launch(void* const* d_in, const int* in_sizes, int n_in,
                              void* d_out, int out_size) {
    const float* x        = (const float*)d_in[0];
    const float* w_router = (const float*)d_in[1];
    const float* w_gate   = (const float*)d_in[2];
    const float* w_up     = (const float*)d_in[3];
    const float* w_down   = (const float*)d_in[4];
    float* out = (float*)d_out;

    cudaFuncSetAttribute(gemm1_kernel, cudaFuncAttributeMaxDynamicSharedMemorySize, G1_SMEM);
    cudaFuncSetAttribute(gemm2_kernel, cudaFuncAttributeMaxDynamicSharedMemorySize, G2_SMEM);

    router_kernel<<<RBLOCKS, 256>>>(x, w_router);                               // 1
    route_kernel<<<1, 1024>>>();                                                // 2
    convert_w_kernel<<<dim3(2048, 1, 24), dim3(32, 8)>>>(w_gate, w_up, w_down); // 3
    gemm1_kernel<<<dim3(FFDIM/64, 64, NEXP), 256, G1_SMEM>>>();                 // 4 <- profiled
    gemm2_kernel<<<dim3(HDIM/128, 64, NEXP), 256, G2_SMEM>>>();                 // 5
    combine_kernel<<<(TOKENS*256)/256, 256>>>(out);                             // 6
    loss_kernel<<<1, 32>>>(out);                                                // 7
}